// round 1
// baseline (speedup 1.0000x reference)
#include <cuda_runtime.h>
#include <cuda_bf16.h>

// ---------------------------------------------------------------------------
// GCN 2-layer forward on GB300.
//   deg[i]   = 1 + #edges with dst==i            (self-loop)
//   dinv[i]  = rsqrt(deg[i])
//   norm[e]  = dinv[src]*dinv[dst]
//   h   = X @ W1
//   o1  = seed(h*dinv^2 + b1) then scatter-add h[src]*norm -> o1[dst]
//   h2  = relu(o1) @ W2      (relu fused into gemm A-read)
//   out = seed(h2*dinv^2 + b2) then scatter-add h2[src]*norm -> out[dst]
// ---------------------------------------------------------------------------

#define MAX_N 50000
#define MAX_E 800000
#define DIM   128

// scratch (device globals -- no allocation allowed)
__device__ float g_deg [MAX_N];
__device__ float g_dinv[MAX_N];
__device__ float g_norm[MAX_E];
__device__ float g_h   [MAX_N * DIM];   // per-layer transformed features
__device__ float g_o1  [MAX_N * DIM];   // layer-1 output

// ---------------------------------------------------------------------------
__global__ void k_deg_init(float* deg, int n) {
    int i = blockIdx.x * blockDim.x + threadIdx.x;
    if (i < n) deg[i] = 1.0f;                    // self-loop contribution
}

__global__ void k_deg_acc(const int* __restrict__ dst, float* deg, int E) {
    int e = blockIdx.x * blockDim.x + threadIdx.x;
    if (e < E) atomicAdd(&deg[dst[e]], 1.0f);
}

__global__ void k_dinv(const float* __restrict__ deg, float* dinv, int n) {
    int i = blockIdx.x * blockDim.x + threadIdx.x;
    if (i < n) dinv[i] = rsqrtf(deg[i]);
}

__global__ void k_norm(const int* __restrict__ src, const int* __restrict__ dst,
                       const float* __restrict__ dinv, float* norm, int E) {
    int e = blockIdx.x * blockDim.x + threadIdx.x;
    if (e < E) norm[e] = dinv[src[e]] * dinv[dst[e]];
}

// ---------------------------------------------------------------------------
// GEMM: C[M,128] = A[M,128] @ B[128,128], optional relu on A read.
// BM=64, BN=128, BK=16, 256 threads, each computes 8x4 microtile.
#define BM 64
#define BN 128
#define BK 16
#define TM 8
#define TN 4

template <bool RELU>
__global__ __launch_bounds__(256) void k_gemm(const float* __restrict__ A,
                                              const float* __restrict__ B,
                                              float* __restrict__ C, int M) {
    __shared__ float As[BM][BK];
    __shared__ float Bs[BK][BN];

    const int tid = threadIdx.x;
    const int m0  = blockIdx.x * BM;
    const int ty  = tid >> 5;   // 0..7   (row group)
    const int tx  = tid & 31;   // 0..31  (col group)

    float acc[TM][TN];
#pragma unroll
    for (int i = 0; i < TM; i++)
#pragma unroll
        for (int j = 0; j < TN; j++) acc[i][j] = 0.0f;

    for (int k0 = 0; k0 < DIM; k0 += BK) {
        // A tile: 64x16 -> one float4 per thread
        {
            int row = tid >> 2;          // 0..63
            int c4  = tid & 3;           // 0..3
            float4 v = make_float4(0.f, 0.f, 0.f, 0.f);
            int gr = m0 + row;
            if (gr < M)
                v = *(const float4*)(A + (long)gr * DIM + k0 + c4 * 4);
            if (RELU) {
                v.x = fmaxf(v.x, 0.f); v.y = fmaxf(v.y, 0.f);
                v.z = fmaxf(v.z, 0.f); v.w = fmaxf(v.w, 0.f);
            }
            *(float4*)(&As[row][c4 * 4]) = v;
        }
        // B tile: 16x128 -> two float4 per thread
#pragma unroll
        for (int t = 0; t < 2; t++) {
            int idx = tid + t * 256;
            int r   = idx >> 5;          // 0..15
            int c4  = idx & 31;          // 0..31
            *(float4*)(&Bs[r][c4 * 4]) =
                *(const float4*)(B + (long)(k0 + r) * DIM + c4 * 4);
        }
        __syncthreads();

#pragma unroll
        for (int k = 0; k < BK; k++) {
            float4 bv = *(const float4*)(&Bs[k][tx * 4]);   // LDS.128, no conflicts
            float b0 = bv.x, b1 = bv.y, b2 = bv.z, b3 = bv.w;
#pragma unroll
            for (int i = 0; i < TM; i++) {
                float a = As[ty * TM + i][k];               // warp-uniform broadcast
                acc[i][0] += a * b0;
                acc[i][1] += a * b1;
                acc[i][2] += a * b2;
                acc[i][3] += a * b3;
            }
        }
        __syncthreads();
    }

#pragma unroll
    for (int i = 0; i < TM; i++) {
        int gr = m0 + ty * TM + i;
        if (gr < M) {
            float4 v = make_float4(acc[i][0], acc[i][1], acc[i][2], acc[i][3]);
            *(float4*)(C + (long)gr * DIM + tx * 4) = v;
        }
    }
}

// ---------------------------------------------------------------------------
// seed: out[i,:] = h[i,:] * dinv[i]^2 + b[:]
// one thread per float4 (N*32 threads). Fully initializes out.
__global__ void k_seed(const float* __restrict__ h, const float* __restrict__ dinv,
                       const float* __restrict__ b, float* __restrict__ out, int n) {
    int idx = blockIdx.x * blockDim.x + threadIdx.x;
    int total = n * (DIM / 4);
    if (idx >= total) return;
    int node = idx >> 5;         // DIM/4 == 32 float4 per row
    int c4   = idx & 31;
    float di = dinv[node];
    float w  = di * di;
    float4 hv = ((const float4*)h)[idx];
    float4 bv = ((const float4*)b)[c4];
    float4 o;
    o.x = hv.x * w + bv.x;
    o.y = hv.y * w + bv.y;
    o.z = hv.z * w + bv.z;
    o.w = hv.w * w + bv.w;
    ((float4*)out)[idx] = o;
}

// ---------------------------------------------------------------------------
// scatter: warp per edge. lane l handles float4 chunk l of the 128-wide row.
// out[dst] += h[src] * norm  via red.global.add.v4.f32 (sm_90+).
__global__ __launch_bounds__(256) void k_scatter(const float* __restrict__ h,
                                                 const int* __restrict__ src,
                                                 const int* __restrict__ dst,
                                                 const float* __restrict__ norm,
                                                 float* __restrict__ out, int E) {
    int warp = (blockIdx.x * blockDim.x + threadIdx.x) >> 5;
    int lane = threadIdx.x & 31;
    if (warp >= E) return;
    int   s = __ldg(&src[warp]);
    int   d = __ldg(&dst[warp]);
    float w = __ldg(&norm[warp]);

    float4 v = ((const float4*)h)[(long)s * 32 + lane];
    v.x *= w; v.y *= w; v.z *= w; v.w *= w;

    float4* addr = ((float4*)out) + (long)d * 32 + lane;
    asm volatile("red.global.add.v4.f32 [%0], {%1, %2, %3, %4};"
                 :: "l"(addr), "f"(v.x), "f"(v.y), "f"(v.z), "f"(v.w)
                 : "memory");
}

// ---------------------------------------------------------------------------
extern "C" void kernel_launch(void* const* d_in, const int* in_sizes, int n_in,
                              void* d_out, int out_size) {
    const float* x  = (const float*)d_in[0];
    const int*   ei = (const int*)  d_in[1];
    const float* W1 = (const float*)d_in[2];
    const float* b1 = (const float*)d_in[3];
    const float* W2 = (const float*)d_in[4];
    const float* b2 = (const float*)d_in[5];
    float* out = (float*)d_out;

    const int N = in_sizes[0] / DIM;
    const int E = in_sizes[1] / 2;
    const int* src = ei;          // edge_index[0]
    const int* dst = ei + E;      // edge_index[1]

    float *deg, *dinv, *norm, *h, *o1;
    cudaGetSymbolAddress((void**)&deg,  g_deg);
    cudaGetSymbolAddress((void**)&dinv, g_dinv);
    cudaGetSymbolAddress((void**)&norm, g_norm);
    cudaGetSymbolAddress((void**)&h,    g_h);
    cudaGetSymbolAddress((void**)&o1,   g_o1);

    const int T = 256;
    // ---- degree / normalization (shared by both layers) ----
    k_deg_init<<<(N + T - 1) / T, T>>>(deg, N);
    k_deg_acc <<<(E + T - 1) / T, T>>>(dst, deg, E);
    k_dinv    <<<(N + T - 1) / T, T>>>(deg, dinv, N);
    k_norm    <<<(E + T - 1) / T, T>>>(src, dst, dinv, norm, E);

    const int gemm_blocks  = (N + BM - 1) / BM;
    const int seed_blocks  = (N * 32 + T - 1) / T;
    const int scat_blocks  = ((long)E * 32 + T - 1) / T;

    // ---- layer 1 ----
    k_gemm<false><<<gemm_blocks, 256>>>(x, W1, h, N);
    k_seed       <<<seed_blocks, T>>>(h, dinv, b1, o1, N);
    k_scatter    <<<scat_blocks, T>>>(h, src, dst, norm, o1, E);

    // ---- layer 2 (relu fused into gemm A-read) ----
    k_gemm<true> <<<gemm_blocks, 256>>>(o1, W2, h, N);
    k_seed       <<<seed_blocks, T>>>(h, dinv, b2, out, N);
    k_scatter    <<<scat_blocks, T>>>(h, src, dst, norm, out, E);
}

// round 2
// speedup vs baseline: 1.5331x; 1.5331x over previous
#include <cuda_runtime.h>
#include <cuda_bf16.h>

// ---------------------------------------------------------------------------
// GCN 2-layer forward on GB300, CSR pull-aggregation version.
//   deg_i[i] = #edges with dst==i ; dinv = rsqrt(deg_i+1)
//   CSR (by dst): ptr/csr_src/csr_nrm built once, reused by both layers.
//   h   = X @ W1
//   o1[i] = h[i]*dinv[i]^2 + b1 + sum_j h[src_j]*nrm_j        (warp per node)
//   h2  = relu(o1) @ W2   (relu fused into GEMM A read)
//   out[i] = h2[i]*dinv[i]^2 + b2 + sum_j h2[src_j]*nrm_j
// ---------------------------------------------------------------------------

#define MAX_N 50000
#define MAX_E 800000
#define DIM   128
#define SCAN_B 1024

// scratch (device globals -- no allocation allowed)
__device__ int   g_deg  [MAX_N];
__device__ float g_dinv [MAX_N];
__device__ int   g_ptr  [MAX_N + 1];
__device__ int   g_cur  [MAX_N];
__device__ int   g_bsum [64];
__device__ int   g_csrc [MAX_E];
__device__ float g_cnrm [MAX_E];
__device__ float g_h    [MAX_N * DIM];
__device__ float g_o1   [MAX_N * DIM];

// ---------------------------------------------------------------------------
__global__ void k_zero(int* deg, int n) {
    int i = blockIdx.x * blockDim.x + threadIdx.x;
    if (i < n) deg[i] = 0;
}

__global__ void k_count(const int* __restrict__ dst, int* deg, int E) {
    int e = blockIdx.x * blockDim.x + threadIdx.x;
    if (e < E) atomicAdd(&deg[dst[e]], 1);
}

__global__ void k_dinv(const int* __restrict__ deg, float* dinv, int n) {
    int i = blockIdx.x * blockDim.x + threadIdx.x;
    if (i < n) dinv[i] = rsqrtf((float)(deg[i] + 1));
}

// exclusive scan of deg -> ptr, 3 phases
__global__ __launch_bounds__(SCAN_B) void k_scan1(const int* __restrict__ deg,
                                                  int* ptr, int* bsum, int n) {
    __shared__ int s[SCAN_B];
    int t = threadIdx.x;
    int i = blockIdx.x * SCAN_B + t;
    int v = (i < n) ? deg[i] : 0;
    s[t] = v;
    __syncthreads();
    for (int off = 1; off < SCAN_B; off <<= 1) {
        int x = (t >= off) ? s[t - off] : 0;
        __syncthreads();
        s[t] += x;
        __syncthreads();
    }
    if (i < n) ptr[i] = s[t] - v;       // exclusive
    if (t == SCAN_B - 1) bsum[blockIdx.x] = s[t];
}

__global__ void k_scan2(int* bsum, int nb) {
    if (threadIdx.x == 0) {
        int acc = 0;
        for (int b = 0; b < nb; b++) { int v = bsum[b]; bsum[b] = acc; acc += v; }
    }
}

__global__ void k_scan3(int* ptr, const int* __restrict__ bsum, int* cur, int n, int E) {
    int i = blockIdx.x * blockDim.x + threadIdx.x;
    if (i < n) {
        int p = ptr[i] + bsum[i / SCAN_B];
        ptr[i] = p;
        cur[i] = p;
    }
    if (i == 0) ptr[n] = E;
}

__global__ void k_fill(const int* __restrict__ src, const int* __restrict__ dst,
                       const float* __restrict__ dinv, int* cur,
                       int* csrc, float* cnrm, int E) {
    int e = blockIdx.x * blockDim.x + threadIdx.x;
    if (e >= E) return;
    int s = src[e], d = dst[e];
    int pos = atomicAdd(&cur[d], 1);
    csrc[pos] = s;
    cnrm[pos] = dinv[s] * dinv[d];
}

// ---------------------------------------------------------------------------
// GEMM: C[M,128] = A[M,128] @ B[128,128]; BM=128, BK=8, 256 thr, 8x8 microtile.
#define GBM 128
#define GBK 8

template <bool RELU>
__global__ __launch_bounds__(256) void k_gemm(const float* __restrict__ A,
                                              const float* __restrict__ B,
                                              float* __restrict__ C, int M) {
    __shared__ float As[GBK][GBM];
    __shared__ float Bs[GBK][DIM];

    const int tid = threadIdx.x;
    const int m0  = blockIdx.x * GBM;
    const int ty  = tid >> 4;   // 0..15 row group
    const int tx  = tid & 15;   // 0..15 col group

    float acc[8][8];
#pragma unroll
    for (int i = 0; i < 8; i++)
#pragma unroll
        for (int j = 0; j < 8; j++) acc[i][j] = 0.0f;

    for (int k0 = 0; k0 < DIM; k0 += GBK) {
        {   // A tile 128x8: one float4 per thread, stored transposed
            int row = tid >> 1, c4 = tid & 1;
            float4 v = make_float4(0.f, 0.f, 0.f, 0.f);
            int gr = m0 + row;
            if (gr < M)
                v = *(const float4*)(A + (long)gr * DIM + k0 + c4 * 4);
            if (RELU) {
                v.x = fmaxf(v.x, 0.f); v.y = fmaxf(v.y, 0.f);
                v.z = fmaxf(v.z, 0.f); v.w = fmaxf(v.w, 0.f);
            }
            As[c4 * 4 + 0][row] = v.x;
            As[c4 * 4 + 1][row] = v.y;
            As[c4 * 4 + 2][row] = v.z;
            As[c4 * 4 + 3][row] = v.w;
        }
        {   // B tile 8x128: one float4 per thread
            int r = tid >> 5, c4 = tid & 31;
            *(float4*)(&Bs[r][c4 * 4]) =
                *(const float4*)(B + (long)(k0 + r) * DIM + c4 * 4);
        }
        __syncthreads();

#pragma unroll
        for (int k = 0; k < GBK; k++) {
            float a[8], b[8];
            *(float4*)(a)     = *(const float4*)(&As[k][ty * 4]);
            *(float4*)(a + 4) = *(const float4*)(&As[k][ty * 4 + 64]);
            *(float4*)(b)     = *(const float4*)(&Bs[k][tx * 4]);
            *(float4*)(b + 4) = *(const float4*)(&Bs[k][tx * 4 + 64]);
#pragma unroll
            for (int i = 0; i < 8; i++)
#pragma unroll
                for (int j = 0; j < 8; j++)
                    acc[i][j] += a[i] * b[j];
        }
        __syncthreads();
    }

#pragma unroll
    for (int i = 0; i < 8; i++) {
        int gr = m0 + ty * 4 + (i & 3) + (i >> 2) * 64;
        if (gr < M) {
            *(float4*)(C + (long)gr * DIM + tx * 4) =
                make_float4(acc[i][0], acc[i][1], acc[i][2], acc[i][3]);
            *(float4*)(C + (long)gr * DIM + tx * 4 + 64) =
                make_float4(acc[i][4], acc[i][5], acc[i][6], acc[i][7]);
        }
    }
}

// ---------------------------------------------------------------------------
// pull-aggregation: warp per node.
// out[i] = h[i]*dinv[i]^2 + b + sum_{j in csr[i]} h[csr_src[j]] * csr_nrm[j]
__global__ __launch_bounds__(256) void k_agg(const float* __restrict__ h,
                                             const int* __restrict__ ptr,
                                             const int* __restrict__ csrc,
                                             const float* __restrict__ cnrm,
                                             const float* __restrict__ dinv,
                                             const float* __restrict__ b,
                                             float* __restrict__ out, int n) {
    int node = (blockIdx.x * blockDim.x + threadIdx.x) >> 5;
    int lane = threadIdx.x & 31;
    if (node >= n) return;

    const float4* h4 = (const float4*)h;
    float di = dinv[node];
    float w0 = di * di;
    float4 hv = h4[(long)node * 32 + lane];
    float4 bv = ((const float4*)b)[lane];
    float4 acc;
    acc.x = hv.x * w0 + bv.x;
    acc.y = hv.y * w0 + bv.y;
    acc.z = hv.z * w0 + bv.z;
    acc.w = hv.w * w0 + bv.w;

    int beg = ptr[node], end = ptr[node + 1];
    int j = beg;
    for (; j + 3 < end; j += 4) {
        int   s0 = csrc[j],     s1 = csrc[j + 1], s2 = csrc[j + 2], s3 = csrc[j + 3];
        float n0 = cnrm[j],     n1 = cnrm[j + 1], n2 = cnrm[j + 2], n3 = cnrm[j + 3];
        float4 v0 = h4[(long)s0 * 32 + lane];
        float4 v1 = h4[(long)s1 * 32 + lane];
        float4 v2 = h4[(long)s2 * 32 + lane];
        float4 v3 = h4[(long)s3 * 32 + lane];
        acc.x += v0.x * n0; acc.y += v0.y * n0; acc.z += v0.z * n0; acc.w += v0.w * n0;
        acc.x += v1.x * n1; acc.y += v1.y * n1; acc.z += v1.z * n1; acc.w += v1.w * n1;
        acc.x += v2.x * n2; acc.y += v2.y * n2; acc.z += v2.z * n2; acc.w += v2.w * n2;
        acc.x += v3.x * n3; acc.y += v3.y * n3; acc.z += v3.z * n3; acc.w += v3.w * n3;
    }
    for (; j < end; j++) {
        int   s = csrc[j];
        float w = cnrm[j];
        float4 v = h4[(long)s * 32 + lane];
        acc.x += v.x * w; acc.y += v.y * w; acc.z += v.z * w; acc.w += v.w * w;
    }
    ((float4*)out)[(long)node * 32 + lane] = acc;
}

// ---------------------------------------------------------------------------
extern "C" void kernel_launch(void* const* d_in, const int* in_sizes, int n_in,
                              void* d_out, int out_size) {
    const float* x  = (const float*)d_in[0];
    const int*   ei = (const int*)  d_in[1];
    const float* W1 = (const float*)d_in[2];
    const float* b1 = (const float*)d_in[3];
    const float* W2 = (const float*)d_in[4];
    const float* b2 = (const float*)d_in[5];
    float* out = (float*)d_out;

    const int N = in_sizes[0] / DIM;
    const int E = in_sizes[1] / 2;
    const int* src = ei;
    const int* dst = ei + E;

    int *deg, *ptr, *cur, *bsum, *csrc;
    float *dinv, *cnrm, *h, *o1;
    cudaGetSymbolAddress((void**)&deg,  g_deg);
    cudaGetSymbolAddress((void**)&dinv, g_dinv);
    cudaGetSymbolAddress((void**)&ptr,  g_ptr);
    cudaGetSymbolAddress((void**)&cur,  g_cur);
    cudaGetSymbolAddress((void**)&bsum, g_bsum);
    cudaGetSymbolAddress((void**)&csrc, g_csrc);
    cudaGetSymbolAddress((void**)&cnrm, g_cnrm);
    cudaGetSymbolAddress((void**)&h,    g_h);
    cudaGetSymbolAddress((void**)&o1,   g_o1);

    const int T = 256;
    const int nb_scan = (N + SCAN_B - 1) / SCAN_B;

    // ---- CSR + normalization build (shared by both layers) ----
    k_zero <<<(N + T - 1) / T, T>>>(deg, N);
    k_count<<<(E + T - 1) / T, T>>>(dst, deg, E);
    k_dinv <<<(N + T - 1) / T, T>>>(deg, dinv, N);
    k_scan1<<<nb_scan, SCAN_B>>>(deg, ptr, bsum, N);
    k_scan2<<<1, 32>>>(bsum, nb_scan);
    k_scan3<<<(N + T - 1) / T, T>>>(ptr, bsum, cur, N, E);
    k_fill <<<(E + T - 1) / T, T>>>(src, dst, dinv, cur, csrc, cnrm, E);

    const int gemm_blocks = (N + GBM - 1) / GBM;
    const int agg_blocks  = (N * 32 + T - 1) / T;

    // ---- layer 1 ----
    k_gemm<false><<<gemm_blocks, 256>>>(x, W1, h, N);
    k_agg        <<<agg_blocks, T>>>(h, ptr, csrc, cnrm, dinv, b1, o1, N);

    // ---- layer 2 ----
    k_gemm<true> <<<gemm_blocks, 256>>>(o1, W2, h, N);
    k_agg        <<<agg_blocks, T>>>(h, ptr, csrc, cnrm, dinv, b2, out, N);
}

// round 4
// speedup vs baseline: 1.6023x; 1.0451x over previous
#include <cuda_runtime.h>
#include <cuda_bf16.h>

// ---------------------------------------------------------------------------
// GCN 2-layer forward on GB300, CSR pull-aggregation + packed f32x2 GEMM.
// ---------------------------------------------------------------------------

#define MAX_N 50000
#define MAX_E 800000
#define DIM   128
#define SCAN_B 1024

typedef unsigned long long ull;

// scratch (device globals -- no allocation allowed)
__device__ int   g_deg  [MAX_N];
__device__ float g_dinv [MAX_N];
__device__ int   g_ptr  [MAX_N + 1];
__device__ int   g_cur  [MAX_N];
__device__ int   g_bsum [64];
__device__ int   g_csrc [MAX_E];
__device__ float g_cnrm [MAX_E];
__device__ float g_h    [MAX_N * DIM];
__device__ float g_o1   [MAX_N * DIM];

// ---------------------------------------------------------------------------
__device__ __forceinline__ ull fma2(ull a, ull b, ull c) {
    ull d;
    asm("fma.rn.f32x2 %0, %1, %2, %3;" : "=l"(d) : "l"(a), "l"(b), "l"(c));
    return d;
}
__device__ __forceinline__ ull dup2(float x) {
    ull d;
    asm("mov.b64 %0, {%1, %1};" : "=l"(d) : "f"(x));
    return d;
}
__device__ __forceinline__ void unpack2(ull p, float& lo, float& hi) {
    asm("mov.b64 {%0, %1}, %2;" : "=f"(lo), "=f"(hi) : "l"(p));
}

// ---------------------------------------------------------------------------
__global__ void k_count(const int* __restrict__ dst, int* deg, int E) {
    int e = blockIdx.x * blockDim.x + threadIdx.x;
    if (e < E) atomicAdd(&deg[dst[e]], 1);
}

// exclusive scan of deg -> ptr (per-block), emit block sums; also dinv.
__global__ __launch_bounds__(SCAN_B) void k_scan1(const int* __restrict__ deg,
                                                  int* ptr, int* bsum,
                                                  float* dinv, int n) {
    __shared__ int s[SCAN_B];
    int t = threadIdx.x;
    int i = blockIdx.x * SCAN_B + t;
    int v = (i < n) ? deg[i] : 0;
    if (i < n) dinv[i] = rsqrtf((float)(v + 1));
    s[t] = v;
    __syncthreads();
    for (int off = 1; off < SCAN_B; off <<= 1) {
        int x = (t >= off) ? s[t - off] : 0;
        __syncthreads();
        s[t] += x;
        __syncthreads();
    }
    if (i < n) ptr[i] = s[t] - v;       // exclusive within block
    if (t == SCAN_B - 1) bsum[blockIdx.x] = s[t];
}

// add block-prefix (computed in-shared from bsum) -> final ptr, init cur.
__global__ void k_scan3(int* ptr, const int* __restrict__ bsum, int* cur,
                        int n, int E, int nb) {
    __shared__ int spre[64];
    int t = threadIdx.x;
    if (t < 64) {
        int acc = 0;
        for (int b = 0; b < t && b < nb; b++) acc += bsum[b];
        spre[t] = acc;
    }
    __syncthreads();
    int i = blockIdx.x * blockDim.x + t;
    if (i < n) {
        int p = ptr[i] + spre[i / SCAN_B];
        ptr[i] = p;
        cur[i] = p;
    }
    if (i == 0) ptr[n] = E;
}

__global__ void k_fill(const int* __restrict__ src, const int* __restrict__ dst,
                       const float* __restrict__ dinv, int* cur,
                       int* csrc, float* cnrm, int E) {
    int e = blockIdx.x * blockDim.x + threadIdx.x;
    if (e >= E) return;
    int s = src[e], d = dst[e];
    int pos = atomicAdd(&cur[d], 1);
    csrc[pos] = s;
    cnrm[pos] = dinv[s] * dinv[d];
}

// ---------------------------------------------------------------------------
// GEMM: C[M,128] = A[M,128] @ B[128,128]; BM=128, BK=8, 256 thr, 8x8 microtile
// computed as 4x8 packed f32x2 accumulators (FFMA2).
#define GBM 128
#define GBK 8

template <bool RELU>
__global__ __launch_bounds__(256) void k_gemm(const float* __restrict__ A,
                                              const float* __restrict__ B,
                                              float* __restrict__ C, int M) {
    __shared__ float As[GBK][GBM];   // transposed A tile: As[k][row]
    __shared__ float Bs[GBK][DIM];

    const int tid = threadIdx.x;
    const int m0  = blockIdx.x * GBM;
    const int ty  = tid >> 4;   // 0..15 row group (4 rows + 4 rows at +64)
    const int tx  = tid & 15;   // 0..15 col group (4 cols + 4 cols at +64)

    // acc2[ip][j]: ip packs row-pairs {(r0,r1),(r2,r3),(r4,r5),(r6,r7)}
    // where r0..r3 = ty*4+0..3, r4..r7 = 64+ty*4+0..3; j = 8 columns.
    ull acc2[4][8];
#pragma unroll
    for (int ip = 0; ip < 4; ip++)
#pragma unroll
        for (int j = 0; j < 8; j++) acc2[ip][j] = 0ull;

    for (int k0 = 0; k0 < DIM; k0 += GBK) {
        {   // A tile 128x8 -> transposed: one float4 per thread
            int row = tid >> 1, c4 = tid & 1;
            float4 v = make_float4(0.f, 0.f, 0.f, 0.f);
            int gr = m0 + row;
            if (gr < M)
                v = *(const float4*)(A + (long)gr * DIM + k0 + c4 * 4);
            if (RELU) {
                v.x = fmaxf(v.x, 0.f); v.y = fmaxf(v.y, 0.f);
                v.z = fmaxf(v.z, 0.f); v.w = fmaxf(v.w, 0.f);
            }
            As[c4 * 4 + 0][row] = v.x;
            As[c4 * 4 + 1][row] = v.y;
            As[c4 * 4 + 2][row] = v.z;
            As[c4 * 4 + 3][row] = v.w;
        }
        {   // B tile 8x128: one float4 per thread
            int r = tid >> 5, c4 = tid & 31;
            *(float4*)(&Bs[r][c4 * 4]) =
                *(const float4*)(B + (long)(k0 + r) * DIM + c4 * 4);
        }
        __syncthreads();

#pragma unroll
        for (int k = 0; k < GBK; k++) {
            // a row-pairs come pre-packed from smem (16B-aligned LDS.128)
            ulonglong2 aL = *(const ulonglong2*)(&As[k][ty * 4]);
            ulonglong2 aH = *(const ulonglong2*)(&As[k][ty * 4 + 64]);
            float4 bv0 = *(const float4*)(&Bs[k][tx * 4]);
            float4 bv1 = *(const float4*)(&Bs[k][tx * 4 + 64]);
            ull bd[8];
            bd[0] = dup2(bv0.x); bd[1] = dup2(bv0.y);
            bd[2] = dup2(bv0.z); bd[3] = dup2(bv0.w);
            bd[4] = dup2(bv1.x); bd[5] = dup2(bv1.y);
            bd[6] = dup2(bv1.z); bd[7] = dup2(bv1.w);
#pragma unroll
            for (int j = 0; j < 8; j++) {
                acc2[0][j] = fma2(aL.x, bd[j], acc2[0][j]);
                acc2[1][j] = fma2(aL.y, bd[j], acc2[1][j]);
                acc2[2][j] = fma2(aH.x, bd[j], acc2[2][j]);
                acc2[3][j] = fma2(aH.y, bd[j], acc2[3][j]);
            }
        }
        __syncthreads();
    }

    // write out: each acc2[ip][*] holds two rows (lo, hi)
#pragma unroll
    for (int ip = 0; ip < 4; ip++) {
        int baseRow = (ip < 2) ? (ty * 4 + 2 * ip) : (64 + ty * 4 + 2 * (ip - 2));
        float lo[8], hi[8];
#pragma unroll
        for (int j = 0; j < 8; j++) unpack2(acc2[ip][j], lo[j], hi[j]);
        int r0 = m0 + baseRow, r1 = r0 + 1;
        if (r0 < M) {
            *(float4*)(C + (long)r0 * DIM + tx * 4)      = make_float4(lo[0], lo[1], lo[2], lo[3]);
            *(float4*)(C + (long)r0 * DIM + tx * 4 + 64) = make_float4(lo[4], lo[5], lo[6], lo[7]);
        }
        if (r1 < M) {
            *(float4*)(C + (long)r1 * DIM + tx * 4)      = make_float4(hi[0], hi[1], hi[2], hi[3]);
            *(float4*)(C + (long)r1 * DIM + tx * 4 + 64) = make_float4(hi[4], hi[5], hi[6], hi[7]);
        }
    }
}

// ---------------------------------------------------------------------------
// pull-aggregation: warp per node.
__global__ __launch_bounds__(256) void k_agg(const float* __restrict__ h,
                                             const int* __restrict__ ptr,
                                             const int* __restrict__ csrc,
                                             const float* __restrict__ cnrm,
                                             const float* __restrict__ dinv,
                                             const float* __restrict__ b,
                                             float* __restrict__ out, int n) {
    int node = (blockIdx.x * blockDim.x + threadIdx.x) >> 5;
    int lane = threadIdx.x & 31;
    if (node >= n) return;

    const float4* h4 = (const float4*)h;
    float di = dinv[node];
    float w0 = di * di;
    float4 hv = h4[(long)node * 32 + lane];
    float4 bv = ((const float4*)b)[lane];
    float4 acc;
    acc.x = hv.x * w0 + bv.x;
    acc.y = hv.y * w0 + bv.y;
    acc.z = hv.z * w0 + bv.z;
    acc.w = hv.w * w0 + bv.w;

    int beg = ptr[node], end = ptr[node + 1];
    int j = beg;
    for (; j + 3 < end; j += 4) {
        int   s0 = csrc[j],     s1 = csrc[j + 1], s2 = csrc[j + 2], s3 = csrc[j + 3];
        float n0 = cnrm[j],     n1 = cnrm[j + 1], n2 = cnrm[j + 2], n3 = cnrm[j + 3];
        float4 v0 = h4[(long)s0 * 32 + lane];
        float4 v1 = h4[(long)s1 * 32 + lane];
        float4 v2 = h4[(long)s2 * 32 + lane];
        float4 v3 = h4[(long)s3 * 32 + lane];
        acc.x += v0.x * n0; acc.y += v0.y * n0; acc.z += v0.z * n0; acc.w += v0.w * n0;
        acc.x += v1.x * n1; acc.y += v1.y * n1; acc.z += v1.z * n1; acc.w += v1.w * n1;
        acc.x += v2.x * n2; acc.y += v2.y * n2; acc.z += v2.z * n2; acc.w += v2.w * n2;
        acc.x += v3.x * n3; acc.y += v3.y * n3; acc.z += v3.z * n3; acc.w += v3.w * n3;
    }
    for (; j < end; j++) {
        int   s = csrc[j];
        float w = cnrm[j];
        float4 v = h4[(long)s * 32 + lane];
        acc.x += v.x * w; acc.y += v.y * w; acc.z += v.z * w; acc.w += v.w * w;
    }
    ((float4*)out)[(long)node * 32 + lane] = acc;
}

// ---------------------------------------------------------------------------
extern "C" void kernel_launch(void* const* d_in, const int* in_sizes, int n_in,
                              void* d_out, int out_size) {
    const float* x  = (const float*)d_in[0];
    const int*   ei = (const int*)  d_in[1];
    const float* W1 = (const float*)d_in[2];
    const float* b1 = (const float*)d_in[3];
    const float* W2 = (const float*)d_in[4];
    const float* b2 = (const float*)d_in[5];
    float* out = (float*)d_out;

    const int N = in_sizes[0] / DIM;
    const int E = in_sizes[1] / 2;
    const int* src = ei;
    const int* dst = ei + E;

    int *deg, *ptr, *cur, *bsum, *csrc;
    float *dinv, *cnrm, *h, *o1;
    cudaGetSymbolAddress((void**)&deg,  g_deg);
    cudaGetSymbolAddress((void**)&dinv, g_dinv);
    cudaGetSymbolAddress((void**)&ptr,  g_ptr);
    cudaGetSymbolAddress((void**)&cur,  g_cur);
    cudaGetSymbolAddress((void**)&bsum, g_bsum);
    cudaGetSymbolAddress((void**)&csrc, g_csrc);
    cudaGetSymbolAddress((void**)&cnrm, g_cnrm);
    cudaGetSymbolAddress((void**)&h,    g_h);
    cudaGetSymbolAddress((void**)&o1,   g_o1);

    const int T = 256;
    const int nb_scan = (N + SCAN_B - 1) / SCAN_B;

    // ---- CSR + normalization build (shared by both layers) ----
    cudaMemsetAsync(deg, 0, (size_t)N * sizeof(int));
    k_count<<<(E + T - 1) / T, T>>>(dst, deg, E);
    k_scan1<<<nb_scan, SCAN_B>>>(deg, ptr, bsum, dinv, N);
    k_scan3<<<(N + T - 1) / T, T>>>(ptr, bsum, cur, N, E, nb_scan);
    k_fill <<<(E + T - 1) / T, T>>>(src, dst, dinv, cur, csrc, cnrm, E);

    const int gemm_blocks = (N + GBM - 1) / GBM;
    const int agg_blocks  = (N * 32 + T - 1) / T;

    // ---- layer 1 ----
    k_gemm<false><<<gemm_blocks, 256>>>(x, W1, h, N);
    k_agg        <<<agg_blocks, T>>>(h, ptr, csrc, cnrm, dinv, b1, o1, N);

    // ---- layer 2 ----
    k_gemm<true> <<<gemm_blocks, 256>>>(o1, W2, h, N);
    k_agg        <<<agg_blocks, T>>>(h, ptr, csrc, cnrm, dinv, b2, out, N);
}